// round 1
// baseline (speedup 1.0000x reference)
#include <cuda_runtime.h>

#define FEAT  40
#define EDIM  64
#define ADIM  64
#define NPAIR 780          // FEAT*(FEAT-1)/2
#define NT    256

// ---------------------------------------------------------------------------
// Packed f32x2 helpers (Blackwell sm_100a+). ptxas never auto-fuses these.
// ---------------------------------------------------------------------------
__device__ __forceinline__ unsigned long long fma2(unsigned long long a,
                                                   unsigned long long b,
                                                   unsigned long long c) {
    unsigned long long d;
    asm("fma.rn.f32x2 %0, %1, %2, %3;" : "=l"(d) : "l"(a), "l"(b), "l"(c));
    return d;
}
__device__ __forceinline__ unsigned long long mul2(unsigned long long a,
                                                   unsigned long long b) {
    unsigned long long d;
    asm("mul.rn.f32x2 %0, %1, %2;" : "=l"(d) : "l"(a), "l"(b));
    return d;
}
__device__ __forceinline__ float lo32(unsigned long long v) {
    return __uint_as_float((unsigned)v);
}
__device__ __forceinline__ float hi32(unsigned long long v) {
    return __uint_as_float((unsigned)(v >> 32));
}

// W transposed once per launch into a device global: Wt[a][e] = W[e][a].
// Lets every CTA load it coalesced and FMA-loop read it as LDS.128 broadcast.
__device__ float g_Wt[ADIM * EDIM];

__global__ void transpose_W_kernel(const float* __restrict__ W) {
    int idx = blockIdx.x * 1024 + threadIdx.x;   // 0..4095
    if (idx < EDIM * ADIM) {
        int a = idx & 63;
        int e = idx >> 6;
        g_Wt[a * EDIM + e] = W[e * ADIM + a];    // coalesced read, strided write
    }
}

__global__ __launch_bounds__(NT)
void afm_main_kernel(const float* __restrict__ x,
                     const float* __restrict__ bias,
                     const float* __restrict__ h,
                     const float* __restrict__ pw,
                     float* __restrict__ out) {
    __shared__ __align__(16) float xs[FEAT * EDIM];   // 10240 B
    __shared__ __align__(16) float Wt[ADIM * EDIM];   // 16384 B
    __shared__ float bs[ADIM];
    __shared__ float hs[ADIM];
    __shared__ float pws[EDIM];
    __shared__ float sc[NPAIR];                        // scores -> exp weights
    __shared__ unsigned char pii[NPAIR];
    __shared__ unsigned char pjj[NPAIR];
    __shared__ float red[8];
    __shared__ float partial[4 * EDIM];

    const int b   = blockIdx.x;
    const int tid = threadIdx.x;

    // ---------------- Phase 0: stage inputs ----------------
    const float* xb = x + (long)b * FEAT * EDIM;
    for (int i = tid; i < FEAT * EDIM; i += NT) xs[i] = xb[i];
    for (int i = tid; i < ADIM * EDIM; i += NT) Wt[i] = g_Wt[i];
    if (tid < ADIM) { bs[tid] = bias[tid]; hs[tid] = h[tid]; }
    if (tid < EDIM) pws[tid] = pw[tid];
    // pair table (triu_indices order): row i contributes FEAT-1-i pairs
    if (tid < FEAT - 1) {
        int i = tid;
        int base = i * (FEAT - 1) - i * (i - 1) / 2;
        for (int j = i + 1; j < FEAT; j++) {
            pii[base + j - i - 1] = (unsigned char)i;
            pjj[base + j - i - 1] = (unsigned char)j;
        }
    }
    __syncthreads();

    // ---------------- Phase 1: scores (the 13 GFLOP GEMM, packed f32x2) ----
    for (int p = tid; p < NPAIR; p += NT) {
        const int i = pii[p];
        const int j = pjj[p];
        const ulonglong2* xi = (const ulonglong2*)(xs + i * EDIM);
        const ulonglong2* xj = (const ulonglong2*)(xs + j * EDIM);
        unsigned long long bi2[EDIM / 2];   // 32 packed f32x2 regs, reused 64x
        #pragma unroll
        for (int k2 = 0; k2 < 16; k2++) {
            ulonglong2 xa = xi[k2];
            ulonglong2 xc = xj[k2];
            bi2[2 * k2]     = mul2(xa.x, xc.x);
            bi2[2 * k2 + 1] = mul2(xa.y, xc.y);
        }
        float score = 0.f;
        #pragma unroll 4
        for (int a = 0; a < ADIM; a++) {
            const ulonglong2* wrow = (const ulonglong2*)(Wt + a * EDIM);
            unsigned long long acc0 = 0ull, acc1 = 0ull;
            #pragma unroll
            for (int k2 = 0; k2 < 16; k2++) {
                ulonglong2 wv = wrow[k2];     // LDS.128, warp-broadcast
                acc0 = fma2(bi2[2 * k2],     wv.x, acc0);
                acc1 = fma2(bi2[2 * k2 + 1], wv.y, acc1);
            }
            float z = ((lo32(acc0) + hi32(acc0)) + (lo32(acc1) + hi32(acc1))) + bs[a];
            score = fmaf(fmaxf(z, 0.f), hs[a], score);
        }
        sc[p] = score;
    }
    __syncthreads();

    // ---------------- Phase 2: softmax over 780 scores ----------------
    // max
    float m = -3.402823466e38f;
    for (int p = tid; p < NPAIR; p += NT) m = fmaxf(m, sc[p]);
    #pragma unroll
    for (int o = 16; o; o >>= 1) m = fmaxf(m, __shfl_xor_sync(0xffffffffu, m, o));
    if ((tid & 31) == 0) red[tid >> 5] = m;
    __syncthreads();
    if (tid == 0) {
        float mm = red[0];
        #pragma unroll
        for (int w = 1; w < 8; w++) mm = fmaxf(mm, red[w]);
        red[0] = mm;
    }
    __syncthreads();
    m = red[0];
    __syncthreads();   // protect red[] reuse below

    // exp + sum
    float s = 0.f;
    for (int p = tid; p < NPAIR; p += NT) {
        float e0 = expf(sc[p] - m);
        sc[p] = e0;
        s += e0;
    }
    #pragma unroll
    for (int o = 16; o; o >>= 1) s += __shfl_xor_sync(0xffffffffu, s, o);
    if ((tid & 31) == 0) red[tid >> 5] = s;
    __syncthreads();
    if (tid == 0) {
        float ss = red[0];
        #pragma unroll
        for (int w = 1; w < 8; w++) ss += red[w];
        red[0] = ss;
    }
    __syncthreads();
    const float scale = (float)NPAIR / red[0];   // softmax * num_pairs folded in

    // ---------------- Phase 3: weighted pooling + final dot ----------------
    {
        const int e = tid & 63;
        const int g = tid >> 6;          // uniform within each warp
        float acc = 0.f;
        for (int p = g; p < NPAIR; p += 4) {
            float w  = sc[p];            // warp-uniform broadcast
            int   i  = pii[p];
            int   j  = pjj[p];
            acc = fmaf(w, xs[i * EDIM + e] * xs[j * EDIM + e], acc);
        }
        partial[g * EDIM + e] = acc;
    }
    __syncthreads();
    if (tid < EDIM) {
        float pooled = (partial[tid] + partial[EDIM + tid]) +
                       (partial[2 * EDIM + tid] + partial[3 * EDIM + tid]);
        partial[tid] = pooled * scale * pws[tid];
    }
    __syncthreads();
    if (tid < 32) {
        float v = partial[tid] + partial[tid + 32];
        #pragma unroll
        for (int o = 16; o; o >>= 1) v += __shfl_xor_sync(0xffffffffu, v, o);
        if (tid == 0) out[b] = v;
    }
}

extern "C" void kernel_launch(void* const* d_in, const int* in_sizes, int n_in,
                              void* d_out, int out_size) {
    const float* x    = (const float*)d_in[0];
    const float* W    = (const float*)d_in[1];
    const float* bias = (const float*)d_in[2];
    const float* h    = (const float*)d_in[3];
    const float* pw   = (const float*)d_in[4];
    float* out = (float*)d_out;

    int B = in_sizes[0] / (FEAT * EDIM);

    transpose_W_kernel<<<4, 1024>>>(W);
    afm_main_kernel<<<B, NT>>>(x, bias, h, pw, out);
}

// round 2
// speedup vs baseline: 1.3356x; 1.3356x over previous
#include <cuda_runtime.h>

#define FEAT   40
#define EDIM   64
#define ADIM   64
#define NPAIR  780          // FEAT*(FEAT-1)/2
#define NT     256
#define TILE_P 128
#define NTILES 7            // ceil(780/128) -> 896 padded pair slots

// ---------------------------------------------------------------------------
// Packed f32x2 helpers (sm_100a+). ptxas never auto-fuses these.
// ---------------------------------------------------------------------------
__device__ __forceinline__ unsigned long long fma2(unsigned long long a,
                                                   unsigned long long b,
                                                   unsigned long long c) {
    unsigned long long d;
    asm("fma.rn.f32x2 %0, %1, %2, %3;" : "=l"(d) : "l"(a), "l"(b), "l"(c));
    return d;
}
__device__ __forceinline__ unsigned long long pack2(float v) {
    unsigned long long d;
    unsigned u = __float_as_uint(v);
    asm("mov.b64 %0, {%1, %1};" : "=l"(d) : "r"(u));
    return d;
}
__device__ __forceinline__ float lo32(unsigned long long v) {
    return __uint_as_float((unsigned)v);
}
__device__ __forceinline__ float hi32(unsigned long long v) {
    return __uint_as_float((unsigned)(v >> 32));
}

struct __align__(16) Smem {
    float xs[FEAT * EDIM];        // 2560  staged x row-block
    float Ws[EDIM * ADIM];        // 4096  W in native [e][a] layout
    float BIt[EDIM * TILE_P];     // 8192  BI tile, TRANSPOSED: [e][p_local]
    float sc[NPAIR];              // scores -> exp weights
    float scpart[TILE_P * 9];     // per-(pair, a-group) partial scores (pad 9)
    float partial[4 * EDIM];      // pooling partials
    float bs[ADIM];
    float hs[ADIM];
    float pws[EDIM];
    float red[8];
    unsigned char pii[NPAIR];
    unsigned char pjj[NPAIR];
};

__global__ __launch_bounds__(NT, 3)
void afm_main_kernel(const float* __restrict__ x,
                     const float* __restrict__ W,
                     const float* __restrict__ bias,
                     const float* __restrict__ h,
                     const float* __restrict__ pw,
                     float* __restrict__ out) {
    extern __shared__ char smem_raw[];
    Smem* s = reinterpret_cast<Smem*>(smem_raw);

    const int b   = blockIdx.x;
    const int tid = threadIdx.x;

    // ---------------- Phase 0: stage inputs ----------------
    {
        const float4* xb4 = (const float4*)(x + (long)b * FEAT * EDIM);
        float4* xs4 = (float4*)s->xs;
        for (int i = tid; i < FEAT * EDIM / 4; i += NT) xs4[i] = xb4[i];
        const float4* w4 = (const float4*)W;
        float4* ws4 = (float4*)s->Ws;
        for (int i = tid; i < EDIM * ADIM / 4; i += NT) ws4[i] = w4[i];
        if (tid < ADIM) { s->bs[tid] = bias[tid]; s->hs[tid] = h[tid]; }
        if (tid < EDIM) s->pws[tid] = pw[tid];
        if (tid < FEAT - 1) {
            int i = tid;
            int base = i * (FEAT - 1) - i * (i - 1) / 2;
            for (int j = i + 1; j < FEAT; j++) {
                s->pii[base + j - i - 1] = (unsigned char)i;
                s->pjj[base + j - i - 1] = (unsigned char)j;
            }
        }
    }
    __syncthreads();

    const int pg = tid & 31;      // pair-group within tile: pairs 4*pg..4*pg+3
    const int ag = tid >> 5;      // a-group (== warp id): cols 8*ag..8*ag+7
    const int a0 = 8 * ag;

    // ---------------- Phase 1: tiled GEMM + fused ReLU/h epilogue ----------
    for (int tile = 0; tile < NTILES; tile++) {
        // --- build transposed BI tile: BIt[e][pl] = xs[i][e]*xs[j][e] ---
        {
            const int pl   = tid & 127;
            const int half = tid >> 7;          // e-half: 0 -> e 0..31, 1 -> 32..63
            const int p    = tile * TILE_P + pl;
            if (p < NPAIR) {
                const int i = s->pii[p];
                const int j = s->pjj[p];
                const float4* xi = (const float4*)(s->xs + i * EDIM);
                const float4* xj = (const float4*)(s->xs + j * EDIM);
                #pragma unroll
                for (int e4 = half * 8; e4 < half * 8 + 8; e4++) {
                    float4 a = xi[e4];
                    float4 c = xj[e4];
                    int e0 = e4 * 4;
                    s->BIt[(e0 + 0) * TILE_P + pl] = a.x * c.x;
                    s->BIt[(e0 + 1) * TILE_P + pl] = a.y * c.y;
                    s->BIt[(e0 + 2) * TILE_P + pl] = a.z * c.z;
                    s->BIt[(e0 + 3) * TILE_P + pl] = a.w * c.w;
                }
            } else {
                #pragma unroll
                for (int e4 = half * 8; e4 < half * 8 + 8; e4++) {
                    int e0 = e4 * 4;
                    s->BIt[(e0 + 0) * TILE_P + pl] = 0.f;
                    s->BIt[(e0 + 1) * TILE_P + pl] = 0.f;
                    s->BIt[(e0 + 2) * TILE_P + pl] = 0.f;
                    s->BIt[(e0 + 3) * TILE_P + pl] = 0.f;
                }
            }
        }
        __syncthreads();

        // --- register-tiled GEMM: 4 pairs x 8 a per thread, packed f32x2 ---
        unsigned long long acc[4][4];
        #pragma unroll
        for (int q = 0; q < 4; q++)
            #pragma unroll
            for (int t = 0; t < 4; t++) acc[q][t] = 0ull;

        #pragma unroll 2
        for (int e = 0; e < EDIM; e++) {
            float4 bv = *(const float4*)(s->BIt + e * TILE_P + 4 * pg);
            unsigned long long b0 = pack2(bv.x);
            unsigned long long b1 = pack2(bv.y);
            unsigned long long b2 = pack2(bv.z);
            unsigned long long b3 = pack2(bv.w);
            const ulonglong2* wp = (const ulonglong2*)(s->Ws + e * ADIM + a0);
            ulonglong2 wA = wp[0];
            ulonglong2 wB = wp[1];
            acc[0][0] = fma2(b0, wA.x, acc[0][0]);
            acc[0][1] = fma2(b0, wA.y, acc[0][1]);
            acc[0][2] = fma2(b0, wB.x, acc[0][2]);
            acc[0][3] = fma2(b0, wB.y, acc[0][3]);
            acc[1][0] = fma2(b1, wA.x, acc[1][0]);
            acc[1][1] = fma2(b1, wA.y, acc[1][1]);
            acc[1][2] = fma2(b1, wB.x, acc[1][2]);
            acc[1][3] = fma2(b1, wB.y, acc[1][3]);
            acc[2][0] = fma2(b2, wA.x, acc[2][0]);
            acc[2][1] = fma2(b2, wA.y, acc[2][1]);
            acc[2][2] = fma2(b2, wB.x, acc[2][2]);
            acc[2][3] = fma2(b2, wB.y, acc[2][3]);
            acc[3][0] = fma2(b3, wA.x, acc[3][0]);
            acc[3][1] = fma2(b3, wA.y, acc[3][1]);
            acc[3][2] = fma2(b3, wB.x, acc[3][2]);
            acc[3][3] = fma2(b3, wB.y, acc[3][3]);
        }

        // --- fused epilogue: relu(z + b) . h over this thread's 8 a's ---
        #pragma unroll
        for (int q = 0; q < 4; q++) {
            float ssum = 0.f;
            #pragma unroll
            for (int t = 0; t < 4; t++) {
                int a = a0 + 2 * t;
                float z0 = lo32(acc[q][t]) + s->bs[a];
                float z1 = hi32(acc[q][t]) + s->bs[a + 1];
                ssum = fmaf(fmaxf(z0, 0.f), s->hs[a], ssum);
                ssum = fmaf(fmaxf(z1, 0.f), s->hs[a + 1], ssum);
            }
            s->scpart[(4 * pg + q) * 9 + ag] = ssum;
        }
        __syncthreads();

        // --- reduce 8 a-group partials into the score ---
        if (tid < TILE_P) {
            int p = tile * TILE_P + tid;
            if (p < NPAIR) {
                float t0 = 0.f;
                #pragma unroll
                for (int g = 0; g < 8; g++) t0 += s->scpart[tid * 9 + g];
                s->sc[p] = t0;
            }
        }
        __syncthreads();
    }

    // ---------------- Phase 2: softmax over 780 scores ----------------
    float m = -3.402823466e38f;
    for (int p = tid; p < NPAIR; p += NT) m = fmaxf(m, s->sc[p]);
    #pragma unroll
    for (int o = 16; o; o >>= 1) m = fmaxf(m, __shfl_xor_sync(0xffffffffu, m, o));
    if ((tid & 31) == 0) s->red[tid >> 5] = m;
    __syncthreads();
    if (tid == 0) {
        float mm = s->red[0];
        #pragma unroll
        for (int w = 1; w < 8; w++) mm = fmaxf(mm, s->red[w]);
        s->red[0] = mm;
    }
    __syncthreads();
    m = s->red[0];
    __syncthreads();

    float sum = 0.f;
    for (int p = tid; p < NPAIR; p += NT) {
        float e0 = __expf(s->sc[p] - m);
        s->sc[p] = e0;
        sum += e0;
    }
    #pragma unroll
    for (int o = 16; o; o >>= 1) sum += __shfl_xor_sync(0xffffffffu, sum, o);
    if ((tid & 31) == 0) s->red[tid >> 5] = sum;
    __syncthreads();
    if (tid == 0) {
        float ss = s->red[0];
        #pragma unroll
        for (int w = 1; w < 8; w++) ss += s->red[w];
        s->red[0] = ss;
    }
    __syncthreads();
    const float scale = (float)NPAIR / s->red[0];

    // ---------------- Phase 3: weighted pooling + final dot ----------------
    {
        const int e = tid & 63;
        const int g = tid >> 6;
        float acc = 0.f;
        for (int p = g; p < NPAIR; p += 4) {
            float w = s->sc[p];
            int   i = s->pii[p];
            int   j = s->pjj[p];
            acc = fmaf(w, s->xs[i * EDIM + e] * s->xs[j * EDIM + e], acc);
        }
        s->partial[g * EDIM + e] = acc;
    }
    __syncthreads();
    if (tid < EDIM) {
        float pooled = (s->partial[tid] + s->partial[EDIM + tid]) +
                       (s->partial[2 * EDIM + tid] + s->partial[3 * EDIM + tid]);
        s->partial[tid] = pooled * scale * s->pws[tid];
    }
    __syncthreads();
    if (tid < 32) {
        float v = s->partial[tid] + s->partial[tid + 32];
        #pragma unroll
        for (int o = 16; o; o >>= 1) v += __shfl_xor_sync(0xffffffffu, v, o);
        if (tid == 0) out[b] = v;
    }
}

extern "C" void kernel_launch(void* const* d_in, const int* in_sizes, int n_in,
                              void* d_out, int out_size) {
    const float* x    = (const float*)d_in[0];
    const float* W    = (const float*)d_in[1];
    const float* bias = (const float*)d_in[2];
    const float* h    = (const float*)d_in[3];
    const float* pw   = (const float*)d_in[4];
    float* out = (float*)d_out;

    int B = in_sizes[0] / (FEAT * EDIM);
    size_t smem_bytes = sizeof(Smem);

    static bool attr_set = false;
    if (!attr_set) {
        cudaFuncSetAttribute(afm_main_kernel,
                             cudaFuncAttributeMaxDynamicSharedMemorySize,
                             (int)smem_bytes);
        attr_set = true;
    }

    afm_main_kernel<<<B, NT, smem_bytes>>>(x, W, bias, h, pw, out);
}